// round 12
// baseline (speedup 1.0000x reference)
#include <cuda_runtime.h>

#define NBATCH 16
#define NPT    4096
#define NQ     1024
#define NSAMP  32
#define OUT1SZ (NBATCH*3*NQ)
#define OUT2SZ (NBATCH*128*NQ)
#define MAXE   (NBATCH*NQ*NSAMP + 64)
#define FULLM  0xffffffffu

__device__ int      g_fps[NBATCH*NQ];
__device__ unsigned g_ent[MAXE];
__device__ int      g_ecnt;
__device__ float    g_ptsT[NBATCH*NPT*64];   // [b][p][c] transposed points
__device__ float    g_W0[67*64], g_B0[64];
__device__ float    g_W1[64*64], g_B1[64];
__device__ float    g_W2[64*128], g_B2[128];

// ---- f32x2 packed helpers: two independent .rn fp32 ops per instruction --
__device__ __forceinline__ unsigned long long pk2(float a, float b){
    unsigned long long r; asm("mov.b64 %0,{%1,%2};":"=l"(r):"f"(a),"f"(b)); return r;
}
__device__ __forceinline__ void upk2(unsigned long long v, float&a, float&b){
    asm("mov.b64 {%0,%1},%2;":"=f"(a),"=f"(b):"l"(v));
}
__device__ __forceinline__ unsigned long long add2(unsigned long long a, unsigned long long b){
    unsigned long long r; asm("add.rn.f32x2 %0,%1,%2;":"=l"(r):"l"(a),"l"(b)); return r;
}
__device__ __forceinline__ unsigned long long mul2(unsigned long long a, unsigned long long b){
    unsigned long long r; asm("mul.rn.f32x2 %0,%1,%2;":"=l"(r):"l"(a),"l"(b)); return r;
}

// ---------------- prep: zero out2 + fold BN + transpose pts ---------------
__global__ void __launch_bounds__(256) prep_kernel(float* __restrict__ out2,
    const float* __restrict__ pts,
    const float* w0,const float* b0,const float* g0,const float* be0,const float* m0,const float* v0,
    const float* w1,const float* b1,const float* g1,const float* be1,const float* m1,const float* v1,
    const float* w2,const float* b2,const float* g2,const float* be2,const float* m2,const float* v2)
{
    __shared__ float tile[64][65];
    int idx = blockIdx.x*blockDim.x + threadIdx.x;
    if (idx < OUT2SZ/4) ((float4*)out2)[idx] = make_float4(0.f,0.f,0.f,0.f);
    if (blockIdx.x == 0) {
        int t = threadIdx.x;
        if (t == 0) g_ecnt = 0;
        for (int i=t;i<67*64;i+=blockDim.x){int c=i>>6,o=i&63;float s=g0[o]*rsqrtf(v0[o]+1e-5f);g_W0[i]=w0[o*67+c]*s;}
        for (int i=t;i<64*64;i+=blockDim.x){int c=i>>6,o=i&63;float s=g1[o]*rsqrtf(v1[o]+1e-5f);g_W1[i]=w1[o*64+c]*s;}
        for (int i=t;i<64*128;i+=blockDim.x){int k=i>>7,o=i&127;float s=g2[o]*rsqrtf(v2[o]+1e-5f);g_W2[i]=w2[o*64+k]*s;}
        if (t<64){float s=g0[t]*rsqrtf(v0[t]+1e-5f);g_B0[t]=(b0[t]-m0[t])*s+be0[t];}
        if (t<64){float s=g1[t]*rsqrtf(v1[t]+1e-5f);g_B1[t]=(b1[t]-m1[t])*s+be1[t];}
        if (t<128){float s=g2[t]*rsqrtf(v2[t]+1e-5f);g_B2[t]=(b2[t]-m2[t])*s+be2[t];}
    }
    // transpose: CTAs 0..1023 each handle one [64ch x 64pt] tile
    if (blockIdx.x < 1024){
        int b = blockIdx.x >> 6, pt = blockIdx.x & 63;
        int p0 = pt*64;
        const float* src = pts + (size_t)b*64*NPT;
        for (int i=threadIdx.x; i<64*64; i+=256){
            int c = i>>6, pl = i&63;
            tile[c][pl] = src[(size_t)c*NPT + p0 + pl];
        }
        __syncthreads();
        float* dst = g_ptsT + ((size_t)b*NPT + p0)*64;
        for (int i=threadIdx.x; i<64*64; i+=256){
            int pl = i>>6, c = i&63;
            dst[(size_t)pl*64 + c] = tile[c][pl];
        }
    }
}

// ---------------- FPS: 256 thr, packed u64 atomicMax combine --------------
// Cross-warp combine = single smem atomicMax of (val<<32)|(4095-idx) into a
// 4-slot rotating accumulator: max val first, then min index (exact ref tie
// break). Post-barrier chain = one 8B broadcast LDS + extract + coord LDG.
__global__ void __launch_bounds__(256,1) fps_kernel(const float* __restrict__ xyz,
                                                    float* __restrict__ out1)
{
    __shared__ unsigned long long s_best[4];
    int b = blockIdx.x, t = threadIdx.x;
    int lane = t & 31;
    const float* X = xyz + b*3*NPT;
    int base = t*16;
    float px[16],py[16],pz[16],dd[16];
    #pragma unroll
    for (int q=0;q<4;q++){
        float4 a = *(const float4*)(X + base + q*4);
        float4 bv = *(const float4*)(X + NPT + base + q*4);
        float4 c = *(const float4*)(X + 2*NPT + base + q*4);
        px[q*4]=a.x;px[q*4+1]=a.y;px[q*4+2]=a.z;px[q*4+3]=a.w;
        py[q*4]=bv.x;py[q*4+1]=bv.y;py[q*4+2]=bv.z;py[q*4+3]=bv.w;
        pz[q*4]=c.x;pz[q*4+1]=c.y;pz[q*4+2]=c.z;pz[q*4+3]=c.w;
    }
    unsigned long long px2[8],py2[8],pz2[8];
    #pragma unroll
    for (int p=0;p<8;p++){ px2[p]=pk2(px[2*p],px[2*p+1]); py2[p]=pk2(py[2*p],py[2*p+1]); pz2[p]=pk2(pz[2*p],pz[2*p+1]); }
    #pragma unroll
    for (int j=0;j<16;j++) dd[j]=1e10f;
    if (t < 4) s_best[t] = 0ULL;
    __syncthreads();
    int f = 0;
    float cx=__ldg(X), cy=__ldg(X+NPT), cz=__ldg(X+2*NPT);
    for (int it=0; it<NQ; ++it) {
        if (t == 0) g_fps[b*NQ+it] = f;
        unsigned long long ncx=pk2(-cx,-cx), ncy=pk2(-cy,-cy), ncz=pk2(-cz,-cz);
        #pragma unroll
        for (int p=0;p<8;p++){
            // (px-cx)^2+(py-cy)^2+(pz-cz)^2, each op .rn, left-assoc (matches XLA)
            unsigned long long dx=add2(px2[p],ncx), dy=add2(py2[p],ncy), dz=add2(pz2[p],ncz);
            unsigned long long d2=add2(add2(mul2(dx,dx),mul2(dy,dy)),mul2(dz,dz));
            float dlo,dhi; upk2(d2,dlo,dhi);
            dd[2*p]   = fminf(dd[2*p],   dlo);
            dd[2*p+1] = fminf(dd[2*p+1], dhi);
        }
        // stable adjacent-pair argmax tree (ties -> lowest index, matches ref)
        float tv[8]; int tj[8];
        #pragma unroll
        for (int j=0;j<8;j++){
            bool c = dd[2*j+1] > dd[2*j];
            tv[j] = c ? dd[2*j+1] : dd[2*j];
            tj[j] = c ? 2*j+1 : 2*j;
        }
        #pragma unroll
        for (int st=4; st>=1; st>>=1){
            #pragma unroll
            for (int j=0;j<st;j++){
                bool c = tv[2*j+1] > tv[2*j];
                tv[j] = c ? tv[2*j+1] : tv[2*j];
                tj[j] = c ? tj[2*j+1] : tj[2*j];
            }
        }
        float best = tv[0]; int bidx = base + tj[0];
        unsigned db   = __float_as_uint(best);        // >=0: uint order == float order
        unsigned wmax = __reduce_max_sync(FULLM, db);
        unsigned mk   = __ballot_sync(FULLM, db==wmax);
        int src = __ffs(mk)-1;                         // lowest lane = lowest index
        int sl = it & 3;
        if (lane==src){                                // one atomic per warp
            unsigned long long pkd = ((unsigned long long)wmax<<32)
                                   | (unsigned long long)(4095 - bidx);
            atomicMax(&s_best[sl], pkd);
        }
        __syncthreads();
        unsigned long long w = s_best[sl];             // 8B broadcast read
        f = 4095 - (int)(w & 0xFFFULL);
        if (t == 0) s_best[(it+2)&3] = 0ULL;           // next barrier orders this
        cx=__ldg(X+f); cy=__ldg(X+NPT+f); cz=__ldg(X+2*NPT+f);   // broadcast L1 hit
    }
    __syncthreads();
    for (int i=t;i<3*NQ;i+=256){
        int c=i>>10, s=i&1023;
        out1[b*3072 + i] = X[c*NPT + g_fps[b*NQ+s]];
    }
}

// ---------------- ball query: packed f32x2 distance eval ------------------
__global__ void __launch_bounds__(256) bq_kernel(const float* __restrict__ xyz,
                                                 const float* __restrict__ out1)
{
    __shared__ unsigned ebuf[8*128];
    int b = blockIdx.x >> 5, qb = blockIdx.x & 31;
    const float* Xx = xyz + b*3*NPT;
    const float* Xy = Xx + NPT;
    const float* Xz = Xx + 2*NPT;
    int wid = threadIdx.x>>5, lane = threadIdx.x&31;
    unsigned lt = (1u<<lane)-1u;
    unsigned* wbuf = ebuf + wid*128;
    int s0 = qb*32 + wid*4;
    float cx[4],cy[4],cz[4]; int cnt[4]={0,0,0,0}; unsigned gtag[4];
    unsigned long long ncx[4],ncy[4],ncz[4];
    #pragma unroll
    for (int q=0;q<4;q++){
        int s = s0+q;
        cx[q]=__ldg(out1 + b*3072 + s);
        cy[q]=__ldg(out1 + b*3072 + 1024 + s);
        cz[q]=__ldg(out1 + b*3072 + 2048 + s);
        ncx[q]=pk2(-cx[q],-cx[q]); ncy[q]=pk2(-cy[q],-cy[q]); ncz[q]=pk2(-cz[q],-cz[q]);
        gtag[q]=(unsigned)(b*NQ+s)<<12;
    }
    int wn = 0;
    for (int bp=0; bp<NPT; bp+=128){
        if (cnt[0]>=NSAMP && cnt[1]>=NSAMP && cnt[2]>=NSAMP && cnt[3]>=NSAMP) break;
        int p = bp + lane*4;
        float4 fx = __ldg((const float4*)(Xx+p));
        float4 fy = __ldg((const float4*)(Xy+p));
        float4 fz = __ldg((const float4*)(Xz+p));
        unsigned long long pxa=pk2(fx.x,fx.y), pxb=pk2(fx.z,fx.w);
        unsigned long long pya=pk2(fy.x,fy.y), pyb=pk2(fy.z,fy.w);
        unsigned long long pza=pk2(fz.x,fz.y), pzb=pk2(fz.z,fz.w);
        #pragma unroll
        for (int q=0;q<4;q++){
            if (cnt[q]>=NSAMP) continue;          // warp-uniform
            // packed distance eval: bitwise identical to scalar .rn sequence
            unsigned long long dxa=add2(pxa,ncx[q]), dya=add2(pya,ncy[q]), dza=add2(pza,ncz[q]);
            unsigned long long dxb=add2(pxb,ncx[q]), dyb=add2(pyb,ncy[q]), dzb=add2(pzb,ncz[q]);
            unsigned long long sa=add2(add2(mul2(dxa,dxa),mul2(dya,dya)),mul2(dza,dza));
            unsigned long long sb=add2(add2(mul2(dxb,dxb),mul2(dyb,dyb)),mul2(dzb,dzb));
            float d0,d1,d2,d3; upk2(sa,d0,d1); upk2(sb,d2,d3);
            bool inb[4] = { d0<=0.04f, d1<=0.04f, d2<=0.04f, d3<=0.04f };
            unsigned m[4];
            #pragma unroll
            for (int j=0;j<4;j++) m[j] = __ballot_sync(FULLM, inb[j]);
            int tot = __popc(m[0])+__popc(m[1])+__popc(m[2])+__popc(m[3]);
            if (!tot) continue;                    // warp-uniform
            if (cnt[q] + tot <= NSAMP){
                int off = wn;                      // order irrelevant downstream
                #pragma unroll
                for (int j=0;j<4;j++){
                    if (inb[j]) wbuf[off + __popc(m[j]&lt)] = gtag[q] | (unsigned)(p+j);
                    off += __popc(m[j]);
                }
                wn += tot; cnt[q] += tot;
            } else {
                // rare: crossing NSAMP — redo this 128-chunk in index order
                for (int sub=0; sub<4 && cnt[q]<NSAMP; ++sub){
                    int pp = bp + sub*32 + lane;
                    float dx=__ldg(Xx+pp)-cx[q], dy=__ldg(Xy+pp)-cy[q], dz=__ldg(Xz+pp)-cz[q];
                    float dsq = __fadd_rn(__fadd_rn(__fmul_rn(dx,dx),__fmul_rn(dy,dy)),__fmul_rn(dz,dz));
                    bool in = (dsq <= 0.04f);
                    unsigned mask = __ballot_sync(FULLM, in);
                    int pc = __popc(mask);
                    int take = min(pc, NSAMP-cnt[q]);
                    if (in){
                        int pos = __popc(mask & lt);
                        if (pos < take) wbuf[wn+pos] = gtag[q] | (unsigned)pp;
                    }
                    wn += take; cnt[q] += take;
                }
            }
        }
    }
    int gb = 0;
    if (lane==0) gb = atomicAdd(&g_ecnt, wn);
    gb = __shfl_sync(FULLM, gb, 0);
    for (int i=lane;i<wn;i+=32) g_ent[gb+i] = wbuf[i];
}

// ---------------- fused 3-layer MLP + max scatter (4 CTAs/SM) -------------
__global__ void __launch_bounds__(256,4) mlp_kernel(const float* __restrict__ xyz,
                                                    float* __restrict__ out2)
{
    extern __shared__ float sm[];
    float* sX  = sm;            // 67*64 = 4288
    float* sH  = sm + 4288;     // 64*64 = 4096
    float* sB0 = sm + 8384;
    float* sB1 = sm + 8448;
    float* sB2 = sm + 8512;     // total 8640 floats = 34560 B
    int t = threadIdx.x;
    if (t<64){ sB0[t]=g_B0[t]; sB1[t]=g_B1[t]; }
    if (t<128) sB2[t]=g_B2[t];
    int E = g_ecnt;
    int tiles = (E+63)>>6;
    int tx = t&15, ty = t>>4;
    int* outI = (int*)out2;
    int le = t>>2, sub = t&3;
    for (int tb = blockIdx.x; tb < tiles; tb += gridDim.x){
        int tbase = tb<<6;
        __syncthreads();
        {   // gather 67-channel input (4 threads / entry, contiguous pts rows)
            int ge = tbase + le;
            unsigned raw = g_ent[ge < E ? ge : 0] & 0x3FFFFFFu;
            int p = raw & 4095; int g = raw >> 12; int bb = g >> 10;
            const float* pt = g_ptsT + ((size_t)(bb*NPT) + p)*64 + sub*16;
            #pragma unroll
            for (int k=0;k<4;k++){
                float4 v = __ldg((const float4*)(pt + k*4));
                int c = 3 + sub*16 + k*4;
                sX[(c  )*64+le] = v.x;
                sX[(c+1)*64+le] = v.y;
                sX[(c+2)*64+le] = v.z;
                sX[(c+3)*64+le] = v.w;
            }
            if (sub == 0){
                int ci = g_fps[g];
                const float* xc = xyz + (size_t)(bb*3)*NPT;
                #pragma unroll
                for (int c=0;c<3;c++)
                    sX[c*64+le] = __ldg(xc + c*NPT + p) - __ldg(xc + c*NPT + ci);
            }
        }
        __syncthreads();
        // ---- layer 0: 67 -> 64 ----
        float acc[4][4];
        #pragma unroll
        for (int j=0;j<4;j++){ float bb=sB0[ty*4+j];
            #pragma unroll
            for (int i=0;i<4;i++) acc[i][j]=bb; }
        #pragma unroll 4
        for (int k=0;k<67;k++){
            float4 xv = *(const float4*)&sX[k*64+tx*4];
            float4 wv = __ldg((const float4*)&g_W0[k*64+ty*4]);
            float xr[4]={xv.x,xv.y,xv.z,xv.w};
            float wr[4]={wv.x,wv.y,wv.z,wv.w};
            #pragma unroll
            for (int i=0;i<4;i++)
                #pragma unroll
                for (int j=0;j<4;j++) acc[i][j] = fmaf(xr[i],wr[j],acc[i][j]);
        }
        #pragma unroll
        for (int j=0;j<4;j++){
            float4 hv = make_float4(fmaxf(acc[0][j],0.f),fmaxf(acc[1][j],0.f),
                                    fmaxf(acc[2][j],0.f),fmaxf(acc[3][j],0.f));
            *(float4*)&sH[(ty*4+j)*64 + tx*4] = hv;
        }
        __syncthreads();
        // ---- layer 1: 64 -> 64 ----
        #pragma unroll
        for (int j=0;j<4;j++){ float bb=sB1[ty*4+j];
            #pragma unroll
            for (int i=0;i<4;i++) acc[i][j]=bb; }
        #pragma unroll 4
        for (int k=0;k<64;k++){
            float4 xv = *(const float4*)&sH[k*64+tx*4];
            float4 wv = __ldg((const float4*)&g_W1[k*64+ty*4]);
            float xr[4]={xv.x,xv.y,xv.z,xv.w};
            float wr[4]={wv.x,wv.y,wv.z,wv.w};
            #pragma unroll
            for (int i=0;i<4;i++)
                #pragma unroll
                for (int j=0;j<4;j++) acc[i][j] = fmaf(xr[i],wr[j],acc[i][j]);
        }
        #pragma unroll
        for (int j=0;j<4;j++){
            float4 hv = make_float4(fmaxf(acc[0][j],0.f),fmaxf(acc[1][j],0.f),
                                    fmaxf(acc[2][j],0.f),fmaxf(acc[3][j],0.f));
            *(float4*)&sX[(ty*4+j)*64 + tx*4] = hv;
        }
        __syncthreads();
        // ---- layer 2: 64 -> 128, two 4-wide halves (reg pressure) ----
        unsigned gid[4];
        #pragma unroll
        for (int i=0;i<4;i++){
            int ge = tbase + tx*4 + i;
            gid[i] = (ge < E) ? ((g_ent[ge] >> 12) & 0x3FFFu) : 0xFFFFFFFFu;
        }
        #pragma unroll
        for (int h=0; h<2; h++){
            #pragma unroll
            for (int j=0;j<4;j++){ float bb=sB2[ty*8+h*4+j];
                #pragma unroll
                for (int i=0;i<4;i++) acc[i][j]=bb; }
            #pragma unroll 4
            for (int k=0;k<64;k++){
                float4 xv = *(const float4*)&sX[k*64+tx*4];
                float4 wv = __ldg((const float4*)&g_W2[k*128+ty*8+h*4]);
                float xr[4]={xv.x,xv.y,xv.z,xv.w};
                float wr[4]={wv.x,wv.y,wv.z,wv.w};
                #pragma unroll
                for (int i=0;i<4;i++)
                    #pragma unroll
                    for (int j=0;j<4;j++) acc[i][j]=fmaf(xr[i],wr[j],acc[i][j]);
            }
            #pragma unroll
            for (int i=0;i<4;i++){
                if (gid[i]==0xFFFFFFFFu) continue;
                if (i>0 && gid[i]==gid[i-1]) continue;   // merged into earlier head
                float mv[4];
                #pragma unroll
                for (int j=0;j<4;j++) mv[j]=acc[i][j];
                #pragma unroll
                for (int i2=1;i2<4;i2++){
                    if (i+i2<4 && gid[i+i2]==gid[i]){
                        #pragma unroll
                        for (int j=0;j<4;j++) mv[j]=fmaxf(mv[j],acc[i+i2][j]);
                    }
                }
                int bb = gid[i]>>10, s = gid[i]&1023;
                int* po = outI + (bb*128 + ty*8 + h*4)*NQ + s;
                #pragma unroll
                for (int j=0;j<4;j++)
                    atomicMax(po + j*NQ, __float_as_int(fmaxf(mv[j],0.f)));
            }
        }
    }
}

extern "C" void kernel_launch(void* const* d_in, const int* in_sizes, int n_in,
                              void* d_out, int out_size)
{
    const float* xyz = (const float*)d_in[0];
    const float* pts = (const float*)d_in[1];
    float* out1 = (float*)d_out;
    float* out2 = out1 + OUT1SZ;

    prep_kernel<<<2048,256>>>(out2, pts,
        (const float*)d_in[2],(const float*)d_in[3],(const float*)d_in[4],
        (const float*)d_in[5],(const float*)d_in[6],(const float*)d_in[7],
        (const float*)d_in[8],(const float*)d_in[9],(const float*)d_in[10],
        (const float*)d_in[11],(const float*)d_in[12],(const float*)d_in[13],
        (const float*)d_in[14],(const float*)d_in[15],(const float*)d_in[16],
        (const float*)d_in[17],(const float*)d_in[18],(const float*)d_in[19]);
    fps_kernel<<<16,256>>>(xyz, out1);
    bq_kernel<<<512,256>>>(xyz, out1);
    mlp_kernel<<<592,256,34560>>>(xyz, out2);
}

// round 13
// speedup vs baseline: 1.1098x; 1.1098x over previous
#include <cuda_runtime.h>

#define NBATCH 16
#define NPT    4096
#define NQ     1024
#define NSAMP  32
#define OUT1SZ (NBATCH*3*NQ)
#define OUT2SZ (NBATCH*128*NQ)
#define MAXE   (NBATCH*NQ*NSAMP + 64)
#define FULLM  0xffffffffu

__device__ int      g_fps[NBATCH*NQ];
__device__ unsigned g_ent[MAXE];
__device__ int      g_ecnt;
__device__ float    g_ptsT[NBATCH*NPT*64];   // [b][p][c] transposed points
__device__ float    g_W0[67*64], g_B0[64];
__device__ float    g_W1[64*64], g_B1[64];
__device__ float    g_W2[64*128], g_B2[128];

// ---- f32x2 packed helpers: two independent .rn fp32 ops per instruction --
__device__ __forceinline__ unsigned long long pk2(float a, float b){
    unsigned long long r; asm("mov.b64 %0,{%1,%2};":"=l"(r):"f"(a),"f"(b)); return r;
}
__device__ __forceinline__ void upk2(unsigned long long v, float&a, float&b){
    asm("mov.b64 {%0,%1},%2;":"=f"(a),"=f"(b):"l"(v));
}
__device__ __forceinline__ unsigned long long add2(unsigned long long a, unsigned long long b){
    unsigned long long r; asm("add.rn.f32x2 %0,%1,%2;":"=l"(r):"l"(a),"l"(b)); return r;
}
__device__ __forceinline__ unsigned long long mul2(unsigned long long a, unsigned long long b){
    unsigned long long r; asm("mul.rn.f32x2 %0,%1,%2;":"=l"(r):"l"(a),"l"(b)); return r;
}
__device__ __forceinline__ unsigned long long umax64(unsigned long long a, unsigned long long b){
    return a > b ? a : b;
}

// ---------------- prep: zero out2 + fold BN + transpose pts ---------------
__global__ void __launch_bounds__(256) prep_kernel(float* __restrict__ out2,
    const float* __restrict__ pts,
    const float* w0,const float* b0,const float* g0,const float* be0,const float* m0,const float* v0,
    const float* w1,const float* b1,const float* g1,const float* be1,const float* m1,const float* v1,
    const float* w2,const float* b2,const float* g2,const float* be2,const float* m2,const float* v2)
{
    __shared__ float tile[64][65];
    int idx = blockIdx.x*blockDim.x + threadIdx.x;
    if (idx < OUT2SZ/4) ((float4*)out2)[idx] = make_float4(0.f,0.f,0.f,0.f);
    if (blockIdx.x == 0) {
        int t = threadIdx.x;
        if (t == 0) g_ecnt = 0;
        for (int i=t;i<67*64;i+=blockDim.x){int c=i>>6,o=i&63;float s=g0[o]*rsqrtf(v0[o]+1e-5f);g_W0[i]=w0[o*67+c]*s;}
        for (int i=t;i<64*64;i+=blockDim.x){int c=i>>6,o=i&63;float s=g1[o]*rsqrtf(v1[o]+1e-5f);g_W1[i]=w1[o*64+c]*s;}
        for (int i=t;i<64*128;i+=blockDim.x){int k=i>>7,o=i&127;float s=g2[o]*rsqrtf(v2[o]+1e-5f);g_W2[i]=w2[o*64+k]*s;}
        if (t<64){float s=g0[t]*rsqrtf(v0[t]+1e-5f);g_B0[t]=(b0[t]-m0[t])*s+be0[t];}
        if (t<64){float s=g1[t]*rsqrtf(v1[t]+1e-5f);g_B1[t]=(b1[t]-m1[t])*s+be1[t];}
        if (t<128){float s=g2[t]*rsqrtf(v2[t]+1e-5f);g_B2[t]=(b2[t]-m2[t])*s+be2[t];}
    }
    // transpose: CTAs 0..1023 each handle one [64ch x 64pt] tile
    if (blockIdx.x < 1024){
        int b = blockIdx.x >> 6, pt = blockIdx.x & 63;
        int p0 = pt*64;
        const float* src = pts + (size_t)b*64*NPT;
        for (int i=threadIdx.x; i<64*64; i+=256){
            int c = i>>6, pl = i&63;
            tile[c][pl] = src[(size_t)c*NPT + p0 + pl];
        }
        __syncthreads();
        float* dst = g_ptsT + ((size_t)b*NPT + p0)*64;
        for (int i=threadIdx.x; i<64*64; i+=256){
            int pl = i>>6, c = i&63;
            dst[(size_t)pl*64 + c] = tile[c][pl];
        }
    }
}

// ---------------- FPS: 256 thr; stage2 = 8-key LDS.128 + u64 max tree -----
// Winner lane per warp stores packed (val<<32)|(4095-idx) key (u64 ordering
// == max val then min idx == exact ref tie-break). After the barrier every
// thread loads all 8 keys with 4 overlapping LDS.128 and reduces in registers
// (no redux/ballot/atomics in stage 2).
__global__ void __launch_bounds__(256,1) fps_kernel(const float* __restrict__ xyz,
                                                    float* __restrict__ out1)
{
    __shared__ __align__(16) unsigned long long s_key[2][8];
    int b = blockIdx.x, t = threadIdx.x;
    int lane = t & 31, wid = t >> 5;
    const float* X = xyz + b*3*NPT;
    int base = t*16;
    float px[16],py[16],pz[16],dd[16];
    #pragma unroll
    for (int q=0;q<4;q++){
        float4 a = *(const float4*)(X + base + q*4);
        float4 bv = *(const float4*)(X + NPT + base + q*4);
        float4 c = *(const float4*)(X + 2*NPT + base + q*4);
        px[q*4]=a.x;px[q*4+1]=a.y;px[q*4+2]=a.z;px[q*4+3]=a.w;
        py[q*4]=bv.x;py[q*4+1]=bv.y;py[q*4+2]=bv.z;py[q*4+3]=bv.w;
        pz[q*4]=c.x;pz[q*4+1]=c.y;pz[q*4+2]=c.z;pz[q*4+3]=c.w;
    }
    unsigned long long px2[8],py2[8],pz2[8];
    #pragma unroll
    for (int p=0;p<8;p++){ px2[p]=pk2(px[2*p],px[2*p+1]); py2[p]=pk2(py[2*p],py[2*p+1]); pz2[p]=pk2(pz[2*p],pz[2*p+1]); }
    #pragma unroll
    for (int j=0;j<16;j++) dd[j]=1e10f;
    int f = 0;
    float cx=__ldg(X), cy=__ldg(X+NPT), cz=__ldg(X+2*NPT);
    for (int it=0; it<NQ; ++it) {
        if (t == 0) g_fps[b*NQ+it] = f;
        unsigned long long ncx=pk2(-cx,-cx), ncy=pk2(-cy,-cy), ncz=pk2(-cz,-cz);
        #pragma unroll
        for (int p=0;p<8;p++){
            // (px-cx)^2+(py-cy)^2+(pz-cz)^2, each op .rn, left-assoc (matches XLA)
            unsigned long long dx=add2(px2[p],ncx), dy=add2(py2[p],ncy), dz=add2(pz2[p],ncz);
            unsigned long long d2=add2(add2(mul2(dx,dx),mul2(dy,dy)),mul2(dz,dz));
            float dlo,dhi; upk2(d2,dlo,dhi);
            dd[2*p]   = fminf(dd[2*p],   dlo);
            dd[2*p+1] = fminf(dd[2*p+1], dhi);
        }
        // stable adjacent-pair argmax tree (ties -> lowest index, matches ref)
        float tv[8]; int tj[8];
        #pragma unroll
        for (int j=0;j<8;j++){
            bool c = dd[2*j+1] > dd[2*j];
            tv[j] = c ? dd[2*j+1] : dd[2*j];
            tj[j] = c ? 2*j+1 : 2*j;
        }
        #pragma unroll
        for (int st=4; st>=1; st>>=1){
            #pragma unroll
            for (int j=0;j<st;j++){
                bool c = tv[2*j+1] > tv[2*j];
                tv[j] = c ? tv[2*j+1] : tv[2*j];
                tj[j] = c ? tj[2*j+1] : tj[2*j];
            }
        }
        float best = tv[0]; int bidx = base + tj[0];
        unsigned db   = __float_as_uint(best);        // >=0: uint order == float order
        unsigned wmax = __reduce_max_sync(FULLM, db);
        unsigned mk   = __ballot_sync(FULLM, db==wmax);
        int src = __ffs(mk)-1;                         // lowest lane = lowest index
        int par = it & 1;
        if (db==wmax && lane==src){                    // winner lane STS.64 its key
            s_key[par][wid] = ((unsigned long long)wmax<<32)
                            | (unsigned long long)(4095 - bidx);
        }
        __syncthreads();
        // stage 2: 4 overlapping LDS.128, 3-level u64 max tree
        unsigned long long k0,k1,k2,k3,k4,k5,k6,k7;
        {
            const ulonglong2* sp = (const ulonglong2*)s_key[par];
            ulonglong2 va = sp[0], vb = sp[1], vc = sp[2], vd = sp[3];
            k0=va.x; k1=va.y; k2=vb.x; k3=vb.y; k4=vc.x; k5=vc.y; k6=vd.x; k7=vd.y;
        }
        unsigned long long m01=umax64(k0,k1), m23=umax64(k2,k3);
        unsigned long long m45=umax64(k4,k5), m67=umax64(k6,k7);
        unsigned long long w = umax64(umax64(m01,m23), umax64(m45,m67));
        f = 4095 - (int)(w & 0xFFFULL);
        cx=__ldg(X+f); cy=__ldg(X+NPT+f); cz=__ldg(X+2*NPT+f);   // broadcast L1 hit
    }
    __syncthreads();
    for (int i=t;i<3*NQ;i+=256){
        int c=i>>10, s=i&1023;
        out1[b*3072 + i] = X[c*NPT + g_fps[b*NQ+s]];
    }
}

// ---------------- ball query: packed f32x2 distance eval ------------------
__global__ void __launch_bounds__(256) bq_kernel(const float* __restrict__ xyz,
                                                 const float* __restrict__ out1)
{
    __shared__ unsigned ebuf[8*128];
    int b = blockIdx.x >> 5, qb = blockIdx.x & 31;
    const float* Xx = xyz + b*3*NPT;
    const float* Xy = Xx + NPT;
    const float* Xz = Xx + 2*NPT;
    int wid = threadIdx.x>>5, lane = threadIdx.x&31;
    unsigned lt = (1u<<lane)-1u;
    unsigned* wbuf = ebuf + wid*128;
    int s0 = qb*32 + wid*4;
    float cx[4],cy[4],cz[4]; int cnt[4]={0,0,0,0}; unsigned gtag[4];
    unsigned long long ncx[4],ncy[4],ncz[4];
    #pragma unroll
    for (int q=0;q<4;q++){
        int s = s0+q;
        cx[q]=__ldg(out1 + b*3072 + s);
        cy[q]=__ldg(out1 + b*3072 + 1024 + s);
        cz[q]=__ldg(out1 + b*3072 + 2048 + s);
        ncx[q]=pk2(-cx[q],-cx[q]); ncy[q]=pk2(-cy[q],-cy[q]); ncz[q]=pk2(-cz[q],-cz[q]);
        gtag[q]=(unsigned)(b*NQ+s)<<12;
    }
    int wn = 0;
    for (int bp=0; bp<NPT; bp+=128){
        if (cnt[0]>=NSAMP && cnt[1]>=NSAMP && cnt[2]>=NSAMP && cnt[3]>=NSAMP) break;
        int p = bp + lane*4;
        float4 fx = __ldg((const float4*)(Xx+p));
        float4 fy = __ldg((const float4*)(Xy+p));
        float4 fz = __ldg((const float4*)(Xz+p));
        unsigned long long pxa=pk2(fx.x,fx.y), pxb=pk2(fx.z,fx.w);
        unsigned long long pya=pk2(fy.x,fy.y), pyb=pk2(fy.z,fy.w);
        unsigned long long pza=pk2(fz.x,fz.y), pzb=pk2(fz.z,fz.w);
        #pragma unroll
        for (int q=0;q<4;q++){
            if (cnt[q]>=NSAMP) continue;          // warp-uniform
            // packed distance eval: bitwise identical to scalar .rn sequence
            unsigned long long dxa=add2(pxa,ncx[q]), dya=add2(pya,ncy[q]), dza=add2(pza,ncz[q]);
            unsigned long long dxb=add2(pxb,ncx[q]), dyb=add2(pyb,ncy[q]), dzb=add2(pzb,ncz[q]);
            unsigned long long sa=add2(add2(mul2(dxa,dxa),mul2(dya,dya)),mul2(dza,dza));
            unsigned long long sb=add2(add2(mul2(dxb,dxb),mul2(dyb,dyb)),mul2(dzb,dzb));
            float d0,d1,d2,d3; upk2(sa,d0,d1); upk2(sb,d2,d3);
            bool inb[4] = { d0<=0.04f, d1<=0.04f, d2<=0.04f, d3<=0.04f };
            unsigned m[4];
            #pragma unroll
            for (int j=0;j<4;j++) m[j] = __ballot_sync(FULLM, inb[j]);
            int tot = __popc(m[0])+__popc(m[1])+__popc(m[2])+__popc(m[3]);
            if (!tot) continue;                    // warp-uniform
            if (cnt[q] + tot <= NSAMP){
                int off = wn;                      // order irrelevant downstream
                #pragma unroll
                for (int j=0;j<4;j++){
                    if (inb[j]) wbuf[off + __popc(m[j]&lt)] = gtag[q] | (unsigned)(p+j);
                    off += __popc(m[j]);
                }
                wn += tot; cnt[q] += tot;
            } else {
                // rare: crossing NSAMP — redo this 128-chunk in index order
                for (int sub=0; sub<4 && cnt[q]<NSAMP; ++sub){
                    int pp = bp + sub*32 + lane;
                    float dx=__ldg(Xx+pp)-cx[q], dy=__ldg(Xy+pp)-cy[q], dz=__ldg(Xz+pp)-cz[q];
                    float dsq = __fadd_rn(__fadd_rn(__fmul_rn(dx,dx),__fmul_rn(dy,dy)),__fmul_rn(dz,dz));
                    bool in = (dsq <= 0.04f);
                    unsigned mask = __ballot_sync(FULLM, in);
                    int pc = __popc(mask);
                    int take = min(pc, NSAMP-cnt[q]);
                    if (in){
                        int pos = __popc(mask & lt);
                        if (pos < take) wbuf[wn+pos] = gtag[q] | (unsigned)pp;
                    }
                    wn += take; cnt[q] += take;
                }
            }
        }
    }
    int gb = 0;
    if (lane==0) gb = atomicAdd(&g_ecnt, wn);
    gb = __shfl_sync(FULLM, gb, 0);
    for (int i=lane;i<wn;i+=32) g_ent[gb+i] = wbuf[i];
}

// ---------------- fused 3-layer MLP + max scatter (4 CTAs/SM) -------------
__global__ void __launch_bounds__(256,4) mlp_kernel(const float* __restrict__ xyz,
                                                    float* __restrict__ out2)
{
    extern __shared__ float sm[];
    float* sX  = sm;            // 67*64 = 4288
    float* sH  = sm + 4288;     // 64*64 = 4096
    float* sB0 = sm + 8384;
    float* sB1 = sm + 8448;
    float* sB2 = sm + 8512;     // total 8640 floats = 34560 B
    int t = threadIdx.x;
    if (t<64){ sB0[t]=g_B0[t]; sB1[t]=g_B1[t]; }
    if (t<128) sB2[t]=g_B2[t];
    int E = g_ecnt;
    int tiles = (E+63)>>6;
    int tx = t&15, ty = t>>4;
    int* outI = (int*)out2;
    int le = t>>2, sub = t&3;
    for (int tb = blockIdx.x; tb < tiles; tb += gridDim.x){
        int tbase = tb<<6;
        __syncthreads();
        {   // gather 67-channel input (4 threads / entry, contiguous pts rows)
            int ge = tbase + le;
            unsigned raw = g_ent[ge < E ? ge : 0] & 0x3FFFFFFu;
            int p = raw & 4095; int g = raw >> 12; int bb = g >> 10;
            const float* pt = g_ptsT + ((size_t)(bb*NPT) + p)*64 + sub*16;
            #pragma unroll
            for (int k=0;k<4;k++){
                float4 v = __ldg((const float4*)(pt + k*4));
                int c = 3 + sub*16 + k*4;
                sX[(c  )*64+le] = v.x;
                sX[(c+1)*64+le] = v.y;
                sX[(c+2)*64+le] = v.z;
                sX[(c+3)*64+le] = v.w;
            }
            if (sub == 0){
                int ci = g_fps[g];
                const float* xc = xyz + (size_t)(bb*3)*NPT;
                #pragma unroll
                for (int c=0;c<3;c++)
                    sX[c*64+le] = __ldg(xc + c*NPT + p) - __ldg(xc + c*NPT + ci);
            }
        }
        __syncthreads();
        // ---- layer 0: 67 -> 64 ----
        float acc[4][4];
        #pragma unroll
        for (int j=0;j<4;j++){ float bb=sB0[ty*4+j];
            #pragma unroll
            for (int i=0;i<4;i++) acc[i][j]=bb; }
        #pragma unroll 4
        for (int k=0;k<67;k++){
            float4 xv = *(const float4*)&sX[k*64+tx*4];
            float4 wv = __ldg((const float4*)&g_W0[k*64+ty*4]);
            float xr[4]={xv.x,xv.y,xv.z,xv.w};
            float wr[4]={wv.x,wv.y,wv.z,wv.w};
            #pragma unroll
            for (int i=0;i<4;i++)
                #pragma unroll
                for (int j=0;j<4;j++) acc[i][j] = fmaf(xr[i],wr[j],acc[i][j]);
        }
        #pragma unroll
        for (int j=0;j<4;j++){
            float4 hv = make_float4(fmaxf(acc[0][j],0.f),fmaxf(acc[1][j],0.f),
                                    fmaxf(acc[2][j],0.f),fmaxf(acc[3][j],0.f));
            *(float4*)&sH[(ty*4+j)*64 + tx*4] = hv;
        }
        __syncthreads();
        // ---- layer 1: 64 -> 64 ----
        #pragma unroll
        for (int j=0;j<4;j++){ float bb=sB1[ty*4+j];
            #pragma unroll
            for (int i=0;i<4;i++) acc[i][j]=bb; }
        #pragma unroll 4
        for (int k=0;k<64;k++){
            float4 xv = *(const float4*)&sH[k*64+tx*4];
            float4 wv = __ldg((const float4*)&g_W1[k*64+ty*4]);
            float xr[4]={xv.x,xv.y,xv.z,xv.w};
            float wr[4]={wv.x,wv.y,wv.z,wv.w};
            #pragma unroll
            for (int i=0;i<4;i++)
                #pragma unroll
                for (int j=0;j<4;j++) acc[i][j] = fmaf(xr[i],wr[j],acc[i][j]);
        }
        #pragma unroll
        for (int j=0;j<4;j++){
            float4 hv = make_float4(fmaxf(acc[0][j],0.f),fmaxf(acc[1][j],0.f),
                                    fmaxf(acc[2][j],0.f),fmaxf(acc[3][j],0.f));
            *(float4*)&sX[(ty*4+j)*64 + tx*4] = hv;
        }
        __syncthreads();
        // ---- layer 2: 64 -> 128, two 4-wide halves (reg pressure) ----
        unsigned gid[4];
        #pragma unroll
        for (int i=0;i<4;i++){
            int ge = tbase + tx*4 + i;
            gid[i] = (ge < E) ? ((g_ent[ge] >> 12) & 0x3FFFu) : 0xFFFFFFFFu;
        }
        #pragma unroll
        for (int h=0; h<2; h++){
            #pragma unroll
            for (int j=0;j<4;j++){ float bb=sB2[ty*8+h*4+j];
                #pragma unroll
                for (int i=0;i<4;i++) acc[i][j]=bb; }
            #pragma unroll 4
            for (int k=0;k<64;k++){
                float4 xv = *(const float4*)&sX[k*64+tx*4];
                float4 wv = __ldg((const float4*)&g_W2[k*128+ty*8+h*4]);
                float xr[4]={xv.x,xv.y,xv.z,xv.w};
                float wr[4]={wv.x,wv.y,wv.z,wv.w};
                #pragma unroll
                for (int i=0;i<4;i++)
                    #pragma unroll
                    for (int j=0;j<4;j++) acc[i][j]=fmaf(xr[i],wr[j],acc[i][j]);
            }
            #pragma unroll
            for (int i=0;i<4;i++){
                if (gid[i]==0xFFFFFFFFu) continue;
                if (i>0 && gid[i]==gid[i-1]) continue;   // merged into earlier head
                float mv[4];
                #pragma unroll
                for (int j=0;j<4;j++) mv[j]=acc[i][j];
                #pragma unroll
                for (int i2=1;i2<4;i2++){
                    if (i+i2<4 && gid[i+i2]==gid[i]){
                        #pragma unroll
                        for (int j=0;j<4;j++) mv[j]=fmaxf(mv[j],acc[i+i2][j]);
                    }
                }
                int bb = gid[i]>>10, s = gid[i]&1023;
                int* po = outI + (bb*128 + ty*8 + h*4)*NQ + s;
                #pragma unroll
                for (int j=0;j<4;j++)
                    atomicMax(po + j*NQ, __float_as_int(fmaxf(mv[j],0.f)));
            }
        }
    }
}

extern "C" void kernel_launch(void* const* d_in, const int* in_sizes, int n_in,
                              void* d_out, int out_size)
{
    const float* xyz = (const float*)d_in[0];
    const float* pts = (const float*)d_in[1];
    float* out1 = (float*)d_out;
    float* out2 = out1 + OUT1SZ;

    prep_kernel<<<2048,256>>>(out2, pts,
        (const float*)d_in[2],(const float*)d_in[3],(const float*)d_in[4],
        (const float*)d_in[5],(const float*)d_in[6],(const float*)d_in[7],
        (const float*)d_in[8],(const float*)d_in[9],(const float*)d_in[10],
        (const float*)d_in[11],(const float*)d_in[12],(const float*)d_in[13],
        (const float*)d_in[14],(const float*)d_in[15],(const float*)d_in[16],
        (const float*)d_in[17],(const float*)d_in[18],(const float*)d_in[19]);
    fps_kernel<<<16,256>>>(xyz, out1);
    bq_kernel<<<512,256>>>(xyz, out1);
    mlp_kernel<<<592,256,34560>>>(xyz, out2);
}